// round 13
// baseline (speedup 1.0000x reference)
#include <cuda_runtime.h>
#include <cuda_fp16.h>
#include <cstdint>
#include <cstddef>

// B=32, N=1024, NI=256, NF=256, H=4.
// s_i and a_b are constant over softmax axis j => cancel. Shared adj =>
//   agg = (adj @ (w.*out)) / (adj @ w),  w = exp(s_j)  (no max shift needed:
//   s ~ N(0,0.14); shift cancels in the ratio anyway).
// GEMM1 (proj) fuses bias, score, exp, and V^T construction into its epilogue.
// GEMM2 is persistent: 296 CTAs stream 2048 tiles through one continuous
// cp.async pipeline (prologue paid once; epilogues overlap next tile's loads).

// ---------------- device scratch ----------------
__device__ __half g_inp_h[(size_t)32768 * 256];   // [ (b,n) ][ i ]
__device__ __half g_Wbt[(size_t)1024 * 256];      // [ c=(h,f) ][ k ]
__device__ __half g_adjh[(size_t)1024 * 1024];    // [ i ][ j ]
__device__ __half g_Vt[(size_t)32768 * 1024];     // [ (b,h,f) ][ j ] = fp16(w*out)
__device__ float  g_wT[1024 * 128];               // w[j][bh]
__device__ float  g_denom[128 * 1024];            // denom[bh][i]

// ---------------- helpers ----------------
__device__ __forceinline__ uint32_t smem_u32(const void* p) {
    return (uint32_t)__cvta_generic_to_shared(p);
}
__device__ __forceinline__ void cpa16(uint32_t dst, const void* src) {
    asm volatile("cp.async.cg.shared.global [%0], [%1], 16;" :: "r"(dst), "l"(src));
}
__device__ __forceinline__ void ldmat_x4(uint32_t& r0, uint32_t& r1, uint32_t& r2, uint32_t& r3, uint32_t addr) {
    asm volatile("ldmatrix.sync.aligned.m8n8.x4.shared.b16 {%0,%1,%2,%3}, [%4];\n"
                 : "=r"(r0), "=r"(r1), "=r"(r2), "=r"(r3) : "r"(addr));
}
__device__ __forceinline__ void mma16816(float* c, const uint32_t* a, const uint32_t* b) {
    asm volatile("mma.sync.aligned.m16n8k16.row.col.f32.f16.f16.f32 "
                 "{%0,%1,%2,%3}, {%4,%5,%6,%7}, {%8,%9}, {%0,%1,%2,%3};\n"
                 : "+f"(c[0]), "+f"(c[1]), "+f"(c[2]), "+f"(c[3])
                 : "r"(a[0]), "r"(a[1]), "r"(a[2]), "r"(a[3]), "r"(b[0]), "r"(b[1]));
}

#define G1_STAGE 40960               // A 64x64 (8KB) + B 256x64 (32KB)
#define G1_DYN   (2 * G1_STAGE)      // 2-stage
#define G2_STAGE 32768               // A 128x64 (16KB) + B 128x64 (16KB)
#define G2_DYN   (3 * G2_STAGE)      // 3-stage
#define G2_NCTA  296                 // 2 CTAs x 148 SMs, one wave
#define G2_NTILE 2048                // 8 (bm) x 256 (cn)

// ---------------- fused conversions (one launch) ----------------
__global__ void k0(const float* __restrict__ inp, const float* __restrict__ Wk,
                   const int* __restrict__ adj) {
    int bid = blockIdx.x, tid = threadIdx.x;
    if (bid < 8192) {                                        // inp: 2M float4
        int v = bid * 256 + tid;
        float4 x = reinterpret_cast<const float4*>(inp)[v];
        __half2 p0 = __floats2half2_rn(x.x, x.y);
        __half2 p1 = __floats2half2_rn(x.z, x.w);
        uint2 u;
        u.x = *reinterpret_cast<uint32_t*>(&p0);
        u.y = *reinterpret_cast<uint32_t*>(&p1);
        reinterpret_cast<uint2*>(g_inp_h)[v] = u;
    } else if (bid < 9216) {                                 // Wk -> [c][k]
        int v = (bid - 8192) * 256 + tid;
        int c = v >> 8, k = v & 255;
        g_Wbt[v] = __float2half(Wk[(c >> 8) * 65536 + k * 256 + (c & 255)]);
    } else {                                                 // adj -> fp16
        int v = (bid - 9216) * 256 + tid;
        g_adjh[v] = __float2half((float)adj[v]);
    }
}

// =====================================================================
// GEMM1: C(32768x1024) = inp_h @ Wbt^T.  CTA 64x256, 4 warps (1x4), BK=64,
// 2-stage cp.async, A+B fragments JIT double-buffered at ks granularity.
// Epilogue: +bias; s from acc fragments; w=exp(s); V^T=fp16(w*C); w out.
// =====================================================================
__global__ void __launch_bounds__(128, 2) g1(
    const float* __restrict__ bias, const float* __restrict__ adst)
{
    constexpr int T = 4;                        // K=256 / 64
    const int tid = threadIdx.x;
    const int lane = tid & 31, w = tid >> 5;
    const int wn = w * 64;                      // warp tile 64x64, wm = 0
    const int cn0 = blockIdx.x * 256;           // head*256
    const int bm0 = blockIdx.y * 64;            // (b,n) rows
    const int b = bm0 >> 10, n0 = bm0 & 1023, bh = b * 4 + blockIdx.x;

    extern __shared__ __align__(128) char smem[];
    const uint32_t sbase = smem_u32(smem);
    __shared__ float s_bias[256], s_adst[256], s_w[64], s_part[4][64];

    s_bias[tid]       = bias[cn0 + tid];
    s_bias[tid + 128] = bias[cn0 + tid + 128];
    s_adst[tid]       = adst[cn0 + tid];
    s_adst[tid + 128] = adst[cn0 + tid + 128];

    float acc[4][8][4];
#pragma unroll
    for (int i = 0; i < 4; i++)
#pragma unroll
        for (int j = 0; j < 8; j++)
#pragma unroll
            for (int k = 0; k < 4; k++) acc[i][j][k] = 0.f;

    auto ldst = [&](int kt, int slot) {
        uint32_t base = sbase + (uint32_t)slot * G1_STAGE;
        const __half* As = g_inp_h + (size_t)bm0 * 256 + kt * 64;
        const __half* Bs = g_Wbt + (size_t)cn0 * 256 + kt * 64;
#pragma unroll
        for (int u = 0; u < 4; u++) {           // A: 64r x 8 chunks
            int idx = u * 128 + tid;
            int r = idx >> 3, c = idx & 7;
            cpa16(base + r * 128 + ((c ^ (r & 7)) << 4), As + (size_t)r * 256 + c * 8);
        }
#pragma unroll
        for (int u = 0; u < 16; u++) {          // B: 256r x 8 chunks
            int idx = u * 128 + tid;
            int r = idx >> 3, c = idx & 7;
            cpa16(base + 8192 + r * 128 + ((c ^ (r & 7)) << 4), Bs + (size_t)r * 256 + c * 8);
        }
        asm volatile("cp.async.commit_group;" ::: "memory");
    };

    auto compute = [&](int slot) {
        uint32_t abase = sbase + (uint32_t)slot * G1_STAGE;
        uint32_t bbase = abase + 8192;
        uint32_t af[2][4][4], bf[2][8][2];      // ks-level double buffers
        auto loadA = [&](int ks, int buf) {
            int chA = ks * 2 + (lane >> 4);
#pragma unroll
            for (int mi = 0; mi < 4; mi++) {
                int r = mi * 16 + (lane & 15);
                ldmat_x4(af[buf][mi][0], af[buf][mi][1], af[buf][mi][2], af[buf][mi][3],
                         abase + r * 128 + ((chA ^ (r & 7)) << 4));
            }
        };
        auto loadB = [&](int ks, int buf) {
            int chB = ks * 2 + ((lane >> 3) & 1);
#pragma unroll
            for (int nj2 = 0; nj2 < 4; nj2++) {
                int r = wn + nj2 * 16 + (lane & 7) + ((lane >> 4) << 3);
                uint32_t r0, r1, r2, r3;
                ldmat_x4(r0, r1, r2, r3, bbase + r * 128 + ((chB ^ (r & 7)) << 4));
                bf[buf][nj2 * 2][0] = r0;     bf[buf][nj2 * 2][1] = r1;
                bf[buf][nj2 * 2 + 1][0] = r2; bf[buf][nj2 * 2 + 1][1] = r3;
            }
        };
        loadA(0, 0); loadB(0, 0);
#pragma unroll
        for (int ks = 0; ks < 4; ks++) {
            if (ks + 1 < 4) { loadA(ks + 1, (ks + 1) & 1); loadB(ks + 1, (ks + 1) & 1); }
#pragma unroll
            for (int mi = 0; mi < 4; mi++)
#pragma unroll
                for (int nj = 0; nj < 8; nj++)
                    mma16816(acc[mi][nj], af[ks & 1][mi], bf[ks & 1][nj]);
        }
    };

    ldst(0, 0);
    for (int t = 0; t < T; t++) {
        asm volatile("cp.async.wait_group 0;" ::: "memory");
        __syncthreads();                        // stage t ready; prev compute done
        if (t + 1 < T) ldst(t + 1, (t + 1) & 1);
        compute(t & 1);
    }
    __syncthreads();                            // smem reuse below

    const int gid = lane >> 2, tig = lane & 3;

    // ---- score partials straight from fragments (fp32) ----
    {
        float p[4][2];
#pragma unroll
        for (int mi = 0; mi < 4; mi++) { p[mi][0] = 0.f; p[mi][1] = 0.f; }
#pragma unroll
        for (int mi = 0; mi < 4; mi++)
#pragma unroll
            for (int nj = 0; nj < 8; nj++) {
                int c = wn + nj * 8 + tig * 2;
                float ad0 = s_adst[c], ad1 = s_adst[c + 1];
                float b0 = s_bias[c], b1 = s_bias[c + 1];
                float* a = acc[mi][nj];
                p[mi][0] += (a[0] + b0) * ad0 + (a[1] + b1) * ad1;
                p[mi][1] += (a[2] + b0) * ad0 + (a[3] + b1) * ad1;
            }
#pragma unroll
        for (int mi = 0; mi < 4; mi++)
#pragma unroll
            for (int h = 0; h < 2; h++) {
                float v = p[mi][h];
                v += __shfl_xor_sync(0xffffffffu, v, 1);
                v += __shfl_xor_sync(0xffffffffu, v, 2);
                p[mi][h] = v;
            }
        if (tig == 0)
#pragma unroll
            for (int mi = 0; mi < 4; mi++) {
                s_part[w][mi * 16 + gid]     = p[mi][0];
                s_part[w][mi * 16 + gid + 8] = p[mi][1];
            }
    }

    // ---- stage bias-added fp16 out^T ----
    __half* sT = (__half*)smem;                 // [256 c][72 m]
#pragma unroll
    for (int mi = 0; mi < 4; mi++)
#pragma unroll
        for (int nj = 0; nj < 8; nj++) {
            int m = mi * 16 + gid, c = wn + nj * 8 + tig * 2;
            float b0 = s_bias[c], b1 = s_bias[c + 1];
            float* a = acc[mi][nj];
            sT[c * 72 + m]           = __float2half(a[0] + b0);
            sT[(c + 1) * 72 + m]     = __float2half(a[1] + b1);
            sT[c * 72 + m + 8]       = __float2half(a[2] + b0);
            sT[(c + 1) * 72 + m + 8] = __float2half(a[3] + b1);
        }
    __syncthreads();
    if (tid < 64) {
        float s = s_part[0][tid] + s_part[1][tid] + s_part[2][tid] + s_part[3][tid];
        float wv = expf(s);                     // no max shift: cancels in ratio
        s_w[tid] = wv;
        g_wT[(n0 + tid) * 128 + bh] = wv;
    }
    __syncthreads();
    {
        int sub = tid & 7, r0 = tid >> 3;       // 8 lanes cover a 128B row segment
#pragma unroll
        for (int q = 0; q < 16; q++) {
            int cc = r0 + q * 16;               // 0..255
            uint4 o = *(uint4*)&sT[cc * 72 + sub * 8];
            __half2* hp = (__half2*)&o;
#pragma unroll
            for (int i = 0; i < 4; i++) {
                float2 f = __half22float2(hp[i]);
                hp[i] = __floats2half2_rn(f.x * s_w[sub * 8 + i * 2],
                                          f.y * s_w[sub * 8 + i * 2 + 1]);
            }
            *(uint4*)&g_Vt[(size_t)(b * 1024 + cn0 + cc) * 1024 + n0 + sub * 8] = o;
        }
    }
}

// =====================================================================
// GEMM2 (persistent): C(1024x32768) = adjh @ Vt^T.  296 CTAs, each streams
// ~7 tiles (128x128, 4 warps 2x2) through ONE continuous 3-stage cp.async
// pipeline indexed by global chunk id. Epilogue: /denom, direct fragment
// stores (no smem, no barriers) -> overlaps next tile's loads.
// =====================================================================
__global__ void __launch_bounds__(128, 2) g2(float* __restrict__ Cout)
{
    const int tid = threadIdx.x;
    const int lane = tid & 31, w = tid >> 5;
    const int wm = (w >> 1) * 64, wn = (w & 1) * 64;
    const int gid = lane >> 2, tig = lane & 3;

    extern __shared__ __align__(128) char smem[];
    const uint32_t sbase = smem_u32(smem);

    const int myN = (G2_NTILE - blockIdx.x + G2_NCTA - 1) / G2_NCTA;  // tiles for this CTA
    const int totalChunks = myN * 16;

    float acc[4][8][4];
#pragma unroll
    for (int i = 0; i < 4; i++)
#pragma unroll
        for (int j = 0; j < 8; j++)
#pragma unroll
            for (int k = 0; k < 4; k++) acc[i][j][k] = 0.f;

    // global chunk c -> tile (blockIdx.x + (c>>4)*296), kt = c & 15
    auto ldst_c = [&](int c) {
        int t = blockIdx.x + (c >> 4) * G2_NCTA;
        int bm0 = (t & 7) * 128, cn0 = (t >> 3) * 128, kt = c & 15;
        uint32_t base = sbase + (uint32_t)(c % 3) * G2_STAGE;
        const __half* As = g_adjh + (size_t)bm0 * 1024 + kt * 64;
        const __half* Bs = g_Vt + (size_t)cn0 * 1024 + kt * 64;
#pragma unroll
        for (int u = 0; u < 8; u++) {           // A: 128r x 8 chunks
            int idx = u * 128 + tid;
            int r = idx >> 3, cc = idx & 7;
            cpa16(base + r * 128 + ((cc ^ (r & 7)) << 4), As + (size_t)r * 1024 + cc * 8);
        }
#pragma unroll
        for (int u = 0; u < 8; u++) {           // B: 128r x 8 chunks
            int idx = u * 128 + tid;
            int r = idx >> 3, cc = idx & 7;
            cpa16(base + 16384 + r * 128 + ((cc ^ (r & 7)) << 4), Bs + (size_t)r * 1024 + cc * 8);
        }
        asm volatile("cp.async.commit_group;" ::: "memory");
    };

    auto compute = [&](int slot) {
        uint32_t abase = sbase + (uint32_t)slot * G2_STAGE;
        uint32_t bbase = abase + 16384;
        uint32_t af[2][4][4], bf[2][8][2];      // ks-level double buffers
        auto loadA = [&](int ks, int buf) {
            int chA = ks * 2 + (lane >> 4);
#pragma unroll
            for (int mi = 0; mi < 4; mi++) {
                int r = wm + mi * 16 + (lane & 15);
                ldmat_x4(af[buf][mi][0], af[buf][mi][1], af[buf][mi][2], af[buf][mi][3],
                         abase + r * 128 + ((chA ^ (r & 7)) << 4));
            }
        };
        auto loadB = [&](int ks, int buf) {
            int chB = ks * 2 + ((lane >> 3) & 1);
#pragma unroll
            for (int nj2 = 0; nj2 < 4; nj2++) {
                int r = wn + nj2 * 16 + (lane & 7) + ((lane >> 4) << 3);
                uint32_t r0, r1, r2, r3;
                ldmat_x4(r0, r1, r2, r3, bbase + r * 128 + ((chB ^ (r & 7)) << 4));
                bf[buf][nj2 * 2][0] = r0;     bf[buf][nj2 * 2][1] = r1;
                bf[buf][nj2 * 2 + 1][0] = r2; bf[buf][nj2 * 2 + 1][1] = r3;
            }
        };
        loadA(0, 0); loadB(0, 0);
#pragma unroll
        for (int ks = 0; ks < 4; ks++) {
            if (ks + 1 < 4) { loadA(ks + 1, (ks + 1) & 1); loadB(ks + 1, (ks + 1) & 1); }
#pragma unroll
            for (int mi = 0; mi < 4; mi++)
#pragma unroll
                for (int nj = 0; nj < 8; nj++)
                    mma16816(acc[mi][nj], af[ks & 1][mi], bf[ks & 1][nj]);
        }
    };

    auto epilogue = [&](int tIdx) {
        int t = blockIdx.x + tIdx * G2_NCTA;
        int bm0 = (t & 7) * 128, cn0 = (t >> 3) * 128;
        int bh = cn0 >> 8, b = cn0 >> 10, cin = cn0 & 1023;
#pragma unroll
        for (int mi = 0; mi < 4; mi++) {
            int m = wm + mi * 16 + gid;
            float rd0 = 1.f / g_denom[bh * 1024 + bm0 + m];
            float rd1 = 1.f / g_denom[bh * 1024 + bm0 + m + 8];
            float* dst0 = Cout + ((size_t)b << 20) + (size_t)(bm0 + m) * 1024 + cin;
            float* dst1 = dst0 + (size_t)8 * 1024;
#pragma unroll
            for (int nj = 0; nj < 8; nj++) {
                int c = wn + nj * 8 + tig * 2;
                float* a = acc[mi][nj];
                *(float2*)(dst0 + c) = make_float2(a[0] * rd0, a[1] * rd0);
                *(float2*)(dst1 + c) = make_float2(a[2] * rd1, a[3] * rd1);
            }
        }
#pragma unroll
        for (int i = 0; i < 4; i++)
#pragma unroll
            for (int j = 0; j < 8; j++)
#pragma unroll
                for (int k = 0; k < 4; k++) acc[i][j][k] = 0.f;
    };

    ldst_c(0);
    ldst_c(1);
    for (int c = 0; c < totalChunks; c++) {
        if (c + 1 < totalChunks) asm volatile("cp.async.wait_group 1;" ::: "memory");
        else                     asm volatile("cp.async.wait_group 0;" ::: "memory");
        __syncthreads();
        compute(c % 3);
        if (c + 2 < totalChunks) ldst_c(c + 2);
        if ((c & 15) == 15) epilogue(c >> 4);   // no smem/barriers: overlaps loads
    }
}

// ---------------- denom[bh][i] = sum_j adj[i][j] * w[bh][j] ----------------
__global__ __launch_bounds__(256) void k4_denom(const int* __restrict__ adj) {
    __shared__ float sadj[8][1024];
    int i0 = blockIdx.x * 8;
    int tid = threadIdx.x;
    for (int t = tid; t < 8 * 1024; t += 256)
        sadj[t >> 10][t & 1023] = (float)adj[(size_t)(i0 + (t >> 10)) * 1024 + (t & 1023)];
    __syncthreads();
    int bh = tid & 127, ii = tid >> 7;
    float acc[4] = {0.f, 0.f, 0.f, 0.f};
#pragma unroll 4
    for (int j = 0; j < 1024; j++) {
        float wv = g_wT[j * 128 + bh];
#pragma unroll
        for (int r = 0; r < 4; r++) acc[r] += sadj[ii + 2 * r][j] * wv;
    }
#pragma unroll
    for (int r = 0; r < 4; r++) g_denom[bh * 1024 + i0 + ii + 2 * r] = acc[r];
}

// ---------------- launch ----------------
extern "C" void kernel_launch(void* const* d_in, const int* in_sizes, int n_in,
                              void* d_out, int out_size) {
    const float* inp   = (const float*)d_in[0];
    const int*   adj   = (const int*)d_in[1];
    const float* Wk    = (const float*)d_in[2];
    const float* bk    = (const float*)d_in[3];
    // d_in[4]=a_src, d_in[6]=a_b cancel in the softmax (constant in j)
    const float* a_dst = (const float*)d_in[5];
    float* out = (float*)d_out;

    cudaFuncSetAttribute(g1, cudaFuncAttributeMaxDynamicSharedMemorySize, G1_DYN);
    cudaFuncSetAttribute(g2, cudaFuncAttributeMaxDynamicSharedMemorySize, G2_DYN);

    k0<<<13312, 256>>>(inp, Wk, adj);
    g1<<<dim3(4, 512), 128, G1_DYN>>>(bk, a_dst);
    k4_denom<<<128, 256>>>(adj);
    g2<<<G2_NCTA, 128, G2_DYN>>>(out);
}

// round 14
// speedup vs baseline: 1.0002x; 1.0002x over previous
#include <cuda_runtime.h>
#include <cuda_fp16.h>
#include <cstdint>
#include <cstddef>

// B=32, N=1024, NI=256, NF=256, H=4.
// s_i and a_b are constant over softmax axis j => cancel. Shared adj =>
//   agg = (adj @ (w.*out)) / (adj @ w),  w = exp(s_j)  (no max shift needed:
//   s ~ N(0,0.14); shift cancels in the ratio anyway).
// GEMM1 (proj) fuses bias, score, exp, and V^T construction into its epilogue.
// GEMM2 is the R12 non-persistent version (persistence regressed in R13),
// with loads issued BEFORE compute each iteration for deeper prefetch.

// ---------------- device scratch ----------------
__device__ __half g_inp_h[(size_t)32768 * 256];   // [ (b,n) ][ i ]
__device__ __half g_Wbt[(size_t)1024 * 256];      // [ c=(h,f) ][ k ]
__device__ __half g_adjh[(size_t)1024 * 1024];    // [ i ][ j ]
__device__ __half g_Vt[(size_t)32768 * 1024];     // [ (b,h,f) ][ j ] = fp16(w*out)
__device__ float  g_wT[1024 * 128];               // w[j][bh]
__device__ float  g_denom[128 * 1024];            // denom[bh][i]

// ---------------- helpers ----------------
__device__ __forceinline__ uint32_t smem_u32(const void* p) {
    return (uint32_t)__cvta_generic_to_shared(p);
}
__device__ __forceinline__ void cpa16(uint32_t dst, const void* src) {
    asm volatile("cp.async.cg.shared.global [%0], [%1], 16;" :: "r"(dst), "l"(src));
}
__device__ __forceinline__ void ldmat_x4(uint32_t& r0, uint32_t& r1, uint32_t& r2, uint32_t& r3, uint32_t addr) {
    asm volatile("ldmatrix.sync.aligned.m8n8.x4.shared.b16 {%0,%1,%2,%3}, [%4];\n"
                 : "=r"(r0), "=r"(r1), "=r"(r2), "=r"(r3) : "r"(addr));
}
__device__ __forceinline__ void mma16816(float* c, const uint32_t* a, const uint32_t* b) {
    asm volatile("mma.sync.aligned.m16n8k16.row.col.f32.f16.f16.f32 "
                 "{%0,%1,%2,%3}, {%4,%5,%6,%7}, {%8,%9}, {%0,%1,%2,%3};\n"
                 : "+f"(c[0]), "+f"(c[1]), "+f"(c[2]), "+f"(c[3])
                 : "r"(a[0]), "r"(a[1]), "r"(a[2]), "r"(a[3]), "r"(b[0]), "r"(b[1]));
}

#define G1_STAGE 40960               // A 64x64 (8KB) + B 256x64 (32KB)
#define G1_DYN   (2 * G1_STAGE)      // 2-stage
#define G2_STAGE 32768               // A 128x64 (16KB) + B 128x64 (16KB)
#define G2_DYN   (3 * G2_STAGE)      // 3-stage

// ---------------- fused conversions (one launch) ----------------
__global__ void k0(const float* __restrict__ inp, const float* __restrict__ Wk,
                   const int* __restrict__ adj) {
    int bid = blockIdx.x, tid = threadIdx.x;
    if (bid < 8192) {                                        // inp: 2M float4
        int v = bid * 256 + tid;
        float4 x = reinterpret_cast<const float4*>(inp)[v];
        __half2 p0 = __floats2half2_rn(x.x, x.y);
        __half2 p1 = __floats2half2_rn(x.z, x.w);
        uint2 u;
        u.x = *reinterpret_cast<uint32_t*>(&p0);
        u.y = *reinterpret_cast<uint32_t*>(&p1);
        reinterpret_cast<uint2*>(g_inp_h)[v] = u;
    } else if (bid < 9216) {                                 // Wk -> [c][k]
        int v = (bid - 8192) * 256 + tid;
        int c = v >> 8, k = v & 255;
        g_Wbt[v] = __float2half(Wk[(c >> 8) * 65536 + k * 256 + (c & 255)]);
    } else {                                                 // adj -> fp16, 4/thread
        int v4 = (bid - 9216) * 256 + tid;                   // 262144 int4 vecs
        int4 a = reinterpret_cast<const int4*>(adj)[v4];
        __half2 p0 = __floats2half2_rn((float)a.x, (float)a.y);
        __half2 p1 = __floats2half2_rn((float)a.z, (float)a.w);
        uint2 u;
        u.x = *reinterpret_cast<uint32_t*>(&p0);
        u.y = *reinterpret_cast<uint32_t*>(&p1);
        reinterpret_cast<uint2*>(g_adjh)[v4] = u;
    }
}

// =====================================================================
// GEMM1: C(32768x1024) = inp_h @ Wbt^T.  CTA 64x256, 4 warps (1x4), BK=64,
// 2-stage cp.async, A+B fragments JIT double-buffered at ks granularity.
// Epilogue: +bias; s from acc fragments; w=exp(s); V^T=fp16(w*C); w out.
// =====================================================================
__global__ void __launch_bounds__(128, 2) g1(
    const float* __restrict__ bias, const float* __restrict__ adst)
{
    constexpr int T = 4;                        // K=256 / 64
    const int tid = threadIdx.x;
    const int lane = tid & 31, w = tid >> 5;
    const int wn = w * 64;                      // warp tile 64x64, wm = 0
    const int cn0 = blockIdx.x * 256;           // head*256
    const int bm0 = blockIdx.y * 64;            // (b,n) rows
    const int b = bm0 >> 10, n0 = bm0 & 1023, bh = b * 4 + blockIdx.x;

    extern __shared__ __align__(128) char smem[];
    const uint32_t sbase = smem_u32(smem);
    __shared__ float s_bias[256], s_adst[256], s_w[64], s_part[4][64];

    s_bias[tid]       = bias[cn0 + tid];
    s_bias[tid + 128] = bias[cn0 + tid + 128];
    s_adst[tid]       = adst[cn0 + tid];
    s_adst[tid + 128] = adst[cn0 + tid + 128];

    float acc[4][8][4];
#pragma unroll
    for (int i = 0; i < 4; i++)
#pragma unroll
        for (int j = 0; j < 8; j++)
#pragma unroll
            for (int k = 0; k < 4; k++) acc[i][j][k] = 0.f;

    auto ldst = [&](int kt, int slot) {
        uint32_t base = sbase + (uint32_t)slot * G1_STAGE;
        const __half* As = g_inp_h + (size_t)bm0 * 256 + kt * 64;
        const __half* Bs = g_Wbt + (size_t)cn0 * 256 + kt * 64;
#pragma unroll
        for (int u = 0; u < 4; u++) {           // A: 64r x 8 chunks
            int idx = u * 128 + tid;
            int r = idx >> 3, c = idx & 7;
            cpa16(base + r * 128 + ((c ^ (r & 7)) << 4), As + (size_t)r * 256 + c * 8);
        }
#pragma unroll
        for (int u = 0; u < 16; u++) {          // B: 256r x 8 chunks
            int idx = u * 128 + tid;
            int r = idx >> 3, c = idx & 7;
            cpa16(base + 8192 + r * 128 + ((c ^ (r & 7)) << 4), Bs + (size_t)r * 256 + c * 8);
        }
        asm volatile("cp.async.commit_group;" ::: "memory");
    };

    auto compute = [&](int slot) {
        uint32_t abase = sbase + (uint32_t)slot * G1_STAGE;
        uint32_t bbase = abase + 8192;
        uint32_t af[2][4][4], bf[2][8][2];      // ks-level double buffers
        auto loadA = [&](int ks, int buf) {
            int chA = ks * 2 + (lane >> 4);
#pragma unroll
            for (int mi = 0; mi < 4; mi++) {
                int r = mi * 16 + (lane & 15);
                ldmat_x4(af[buf][mi][0], af[buf][mi][1], af[buf][mi][2], af[buf][mi][3],
                         abase + r * 128 + ((chA ^ (r & 7)) << 4));
            }
        };
        auto loadB = [&](int ks, int buf) {
            int chB = ks * 2 + ((lane >> 3) & 1);
#pragma unroll
            for (int nj2 = 0; nj2 < 4; nj2++) {
                int r = wn + nj2 * 16 + (lane & 7) + ((lane >> 4) << 3);
                uint32_t r0, r1, r2, r3;
                ldmat_x4(r0, r1, r2, r3, bbase + r * 128 + ((chB ^ (r & 7)) << 4));
                bf[buf][nj2 * 2][0] = r0;     bf[buf][nj2 * 2][1] = r1;
                bf[buf][nj2 * 2 + 1][0] = r2; bf[buf][nj2 * 2 + 1][1] = r3;
            }
        };
        loadA(0, 0); loadB(0, 0);
#pragma unroll
        for (int ks = 0; ks < 4; ks++) {
            if (ks + 1 < 4) { loadA(ks + 1, (ks + 1) & 1); loadB(ks + 1, (ks + 1) & 1); }
#pragma unroll
            for (int mi = 0; mi < 4; mi++)
#pragma unroll
                for (int nj = 0; nj < 8; nj++)
                    mma16816(acc[mi][nj], af[ks & 1][mi], bf[ks & 1][nj]);
        }
    };

    ldst(0, 0);
    for (int t = 0; t < T; t++) {
        asm volatile("cp.async.wait_group 0;" ::: "memory");
        __syncthreads();                        // stage t ready; prev compute done
        if (t + 1 < T) ldst(t + 1, (t + 1) & 1);
        compute(t & 1);
    }
    __syncthreads();                            // smem reuse below

    const int gid = lane >> 2, tig = lane & 3;

    // ---- score partials straight from fragments (fp32) ----
    {
        float p[4][2];
#pragma unroll
        for (int mi = 0; mi < 4; mi++) { p[mi][0] = 0.f; p[mi][1] = 0.f; }
#pragma unroll
        for (int mi = 0; mi < 4; mi++)
#pragma unroll
            for (int nj = 0; nj < 8; nj++) {
                int c = wn + nj * 8 + tig * 2;
                float ad0 = s_adst[c], ad1 = s_adst[c + 1];
                float b0 = s_bias[c], b1 = s_bias[c + 1];
                float* a = acc[mi][nj];
                p[mi][0] += (a[0] + b0) * ad0 + (a[1] + b1) * ad1;
                p[mi][1] += (a[2] + b0) * ad0 + (a[3] + b1) * ad1;
            }
#pragma unroll
        for (int mi = 0; mi < 4; mi++)
#pragma unroll
            for (int h = 0; h < 2; h++) {
                float v = p[mi][h];
                v += __shfl_xor_sync(0xffffffffu, v, 1);
                v += __shfl_xor_sync(0xffffffffu, v, 2);
                p[mi][h] = v;
            }
        if (tig == 0)
#pragma unroll
            for (int mi = 0; mi < 4; mi++) {
                s_part[w][mi * 16 + gid]     = p[mi][0];
                s_part[w][mi * 16 + gid + 8] = p[mi][1];
            }
    }

    // ---- stage bias-added fp16 out^T ----
    __half* sT = (__half*)smem;                 // [256 c][72 m]
#pragma unroll
    for (int mi = 0; mi < 4; mi++)
#pragma unroll
        for (int nj = 0; nj < 8; nj++) {
            int m = mi * 16 + gid, c = wn + nj * 8 + tig * 2;
            float b0 = s_bias[c], b1 = s_bias[c + 1];
            float* a = acc[mi][nj];
            sT[c * 72 + m]           = __float2half(a[0] + b0);
            sT[(c + 1) * 72 + m]     = __float2half(a[1] + b1);
            sT[c * 72 + m + 8]       = __float2half(a[2] + b0);
            sT[(c + 1) * 72 + m + 8] = __float2half(a[3] + b1);
        }
    __syncthreads();
    if (tid < 64) {
        float s = s_part[0][tid] + s_part[1][tid] + s_part[2][tid] + s_part[3][tid];
        float wv = expf(s);                     // no max shift: cancels in ratio
        s_w[tid] = wv;
        g_wT[(n0 + tid) * 128 + bh] = wv;
    }
    __syncthreads();
    {
        int sub = tid & 7, r0 = tid >> 3;       // 8 lanes cover a 128B row segment
#pragma unroll
        for (int q = 0; q < 16; q++) {
            int cc = r0 + q * 16;               // 0..255
            uint4 o = *(uint4*)&sT[cc * 72 + sub * 8];
            __half2* hp = (__half2*)&o;
#pragma unroll
            for (int i = 0; i < 4; i++) {
                float2 f = __half22float2(hp[i]);
                hp[i] = __floats2half2_rn(f.x * s_w[sub * 8 + i * 2],
                                          f.y * s_w[sub * 8 + i * 2 + 1]);
            }
            *(uint4*)&g_Vt[(size_t)(b * 1024 + cn0 + cc) * 1024 + n0 + sub * 8] = o;
        }
    }
}

// =====================================================================
// GEMM2: C(1024x32768) = adjh @ Vt^T.  CTA 128x128, 4 warps (2x2), BK=64,
// 3-stage cp.async (loads issued BEFORE compute: slot (t+2)%3=(t-1)%3 is
// free once barrier(t) passes), A+B fragments ks-double-buffered.
// Epilogue: /denom, direct fragment stores (full 32B sectors).
// =====================================================================
__global__ void __launch_bounds__(128, 2) g2(float* __restrict__ Cout)
{
    constexpr int T = 16;                       // K=1024 / 64
    const int tid = threadIdx.x;
    const int lane = tid & 31, w = tid >> 5;
    const int wm = (w >> 1) * 64, wn = (w & 1) * 64;
    const int bm0 = blockIdx.x * 128;           // i rows (x fastest: B reuse in L2)
    const int cn0 = blockIdx.y * 128;           // (b,h,f) cols
    const int bh = cn0 >> 8, b = cn0 >> 10, cin = cn0 & 1023;

    extern __shared__ __align__(128) char smem[];
    const uint32_t sbase = smem_u32(smem);

    float acc[4][8][4];
#pragma unroll
    for (int i = 0; i < 4; i++)
#pragma unroll
        for (int j = 0; j < 8; j++)
#pragma unroll
            for (int k = 0; k < 4; k++) acc[i][j][k] = 0.f;

    auto ldst = [&](int kt, int slot) {
        uint32_t base = sbase + (uint32_t)slot * G2_STAGE;
        const __half* As = g_adjh + (size_t)bm0 * 1024 + kt * 64;
        const __half* Bs = g_Vt + (size_t)cn0 * 1024 + kt * 64;
#pragma unroll
        for (int u = 0; u < 8; u++) {           // A: 128r x 8 chunks
            int idx = u * 128 + tid;
            int r = idx >> 3, c = idx & 7;
            cpa16(base + r * 128 + ((c ^ (r & 7)) << 4), As + (size_t)r * 1024 + c * 8);
        }
#pragma unroll
        for (int u = 0; u < 8; u++) {           // B: 128r x 8 chunks
            int idx = u * 128 + tid;
            int r = idx >> 3, c = idx & 7;
            cpa16(base + 16384 + r * 128 + ((c ^ (r & 7)) << 4), Bs + (size_t)r * 1024 + c * 8);
        }
        asm volatile("cp.async.commit_group;" ::: "memory");
    };

    auto compute = [&](int slot) {
        uint32_t abase = sbase + (uint32_t)slot * G2_STAGE;
        uint32_t bbase = abase + 16384;
        uint32_t af[2][4][4], bf[2][8][2];      // ks-level double buffers
        auto loadA = [&](int ks, int buf) {
            int chA = ks * 2 + (lane >> 4);
#pragma unroll
            for (int mi = 0; mi < 4; mi++) {
                int r = wm + mi * 16 + (lane & 15);
                ldmat_x4(af[buf][mi][0], af[buf][mi][1], af[buf][mi][2], af[buf][mi][3],
                         abase + r * 128 + ((chA ^ (r & 7)) << 4));
            }
        };
        auto loadB = [&](int ks, int buf) {
            int chB = ks * 2 + ((lane >> 3) & 1);
#pragma unroll
            for (int nj2 = 0; nj2 < 4; nj2++) {
                int r = wn + nj2 * 16 + (lane & 7) + ((lane >> 4) << 3);
                uint32_t r0, r1, r2, r3;
                ldmat_x4(r0, r1, r2, r3, bbase + r * 128 + ((chB ^ (r & 7)) << 4));
                bf[buf][nj2 * 2][0] = r0;     bf[buf][nj2 * 2][1] = r1;
                bf[buf][nj2 * 2 + 1][0] = r2; bf[buf][nj2 * 2 + 1][1] = r3;
            }
        };
        loadA(0, 0); loadB(0, 0);
#pragma unroll
        for (int ks = 0; ks < 4; ks++) {
            if (ks + 1 < 4) { loadA(ks + 1, (ks + 1) & 1); loadB(ks + 1, (ks + 1) & 1); }
#pragma unroll
            for (int mi = 0; mi < 4; mi++)
#pragma unroll
                for (int nj = 0; nj < 8; nj++)
                    mma16816(acc[mi][nj], af[ks & 1][mi], bf[ks & 1][nj]);
        }
    };

    ldst(0, 0);
    ldst(1, 1);
    for (int t = 0; t < T; t++) {
        if (t + 1 < T) asm volatile("cp.async.wait_group 1;" ::: "memory");
        else           asm volatile("cp.async.wait_group 0;" ::: "memory");
        __syncthreads();
        if (t + 2 < T) ldst(t + 2, (t + 2) % 3);   // slot free: compute(t-1) done
        compute(t % 3);
    }

    // ---- epilogue: /denom, direct fragment stores (full 32B sectors) ----
    const int gid = lane >> 2, tig = lane & 3;
#pragma unroll
    for (int mi = 0; mi < 4; mi++) {
        int m = wm + mi * 16 + gid;
        float rd0 = 1.f / g_denom[bh * 1024 + bm0 + m];
        float rd1 = 1.f / g_denom[bh * 1024 + bm0 + m + 8];
        float* dst0 = Cout + ((size_t)b << 20) + (size_t)(bm0 + m) * 1024 + cin;
        float* dst1 = dst0 + (size_t)8 * 1024;
#pragma unroll
        for (int nj = 0; nj < 8; nj++) {
            int c = wn + nj * 8 + tig * 2;
            float* a = acc[mi][nj];
            *(float2*)(dst0 + c) = make_float2(a[0] * rd0, a[1] * rd0);
            *(float2*)(dst1 + c) = make_float2(a[2] * rd1, a[3] * rd1);
        }
    }
}

// ---------------- denom[bh][i] = sum_j adj[i][j] * w[bh][j] ----------------
__global__ __launch_bounds__(256) void k4_denom(const int* __restrict__ adj) {
    __shared__ float sadj[8][1024];
    int i0 = blockIdx.x * 8;
    int tid = threadIdx.x;
    for (int t = tid; t < 8 * 1024; t += 256)
        sadj[t >> 10][t & 1023] = (float)adj[(size_t)(i0 + (t >> 10)) * 1024 + (t & 1023)];
    __syncthreads();
    int bh = tid & 127, ii = tid >> 7;
    float acc[4] = {0.f, 0.f, 0.f, 0.f};
#pragma unroll 4
    for (int j = 0; j < 1024; j++) {
        float wv = g_wT[j * 128 + bh];
#pragma unroll
        for (int r = 0; r < 4; r++) acc[r] += sadj[ii + 2 * r][j] * wv;
    }
#pragma unroll
    for (int r = 0; r < 4; r++) g_denom[bh * 1024 + i0 + ii + 2 * r] = acc[r];
}

// ---------------- launch ----------------
extern "C" void kernel_launch(void* const* d_in, const int* in_sizes, int n_in,
                              void* d_out, int out_size) {
    const float* inp   = (const float*)d_in[0];
    const int*   adj   = (const int*)d_in[1];
    const float* Wk    = (const float*)d_in[2];
    const float* bk    = (const float*)d_in[3];
    // d_in[4]=a_src, d_in[6]=a_b cancel in the softmax (constant in j)
    const float* a_dst = (const float*)d_in[5];
    float* out = (float*)d_out;

    cudaFuncSetAttribute(g1, cudaFuncAttributeMaxDynamicSharedMemorySize, G1_DYN);
    cudaFuncSetAttribute(g2, cudaFuncAttributeMaxDynamicSharedMemorySize, G2_DYN);

    k0<<<10240, 256>>>(inp, Wk, adj);
    g1<<<dim3(4, 512), 128, G1_DYN>>>(bk, a_dst);
    k4_denom<<<128, 256>>>(adj);
    g2<<<dim3(8, 256), 128, G2_DYN>>>(out);
}